// round 3
// baseline (speedup 1.0000x reference)
#include <cuda_runtime.h>
#include <cstdint>

#define NN 100000
#define EE 800000
#define GG 64
#define HH 128
#define FIN 64
#define NBLK ((NN + 1023) / 1024)   // scan blocks = 98

// Scratch (allocation-free rule: __device__ globals)
__device__ __align__(16) float g_u[(size_t)NN * HH];   // aggregated input to GEMM
__device__ __align__(16) float g_z[(size_t)NN * HH];   // GEMM output / activation
__device__ float g_dinv[NN];
__device__ int   g_cnt[NN];
__device__ int   g_off[NN + 1];
__device__ int   g_cur[NN];
__device__ int   g_csr[EE];
__device__ int   g_bsum[128];
__device__ __align__(16) float g_pool[GG * HH + GG];

// ---------------------------------------------------------------------------
__global__ void zero_int_kernel(int* __restrict__ p, int n) {
    int i = blockIdx.x * blockDim.x + threadIdx.x;
    if (i < n) p[i] = 0;
}
__global__ void zero_f_kernel(float* __restrict__ p, int n) {
    int i = blockIdx.x * blockDim.x + threadIdx.x;
    if (i < n) p[i] = 0.0f;
}

__global__ void hist_kernel(const int* __restrict__ ei) {
    int e = blockIdx.x * blockDim.x + threadIdx.x;
    if (e < EE) atomicAdd(&g_cnt[ei[EE + e]], 1);
}

// Block-level scan (1024 elems / block, 256 threads x 4). Also computes dinv.
__global__ void scan1_kernel() {
    __shared__ int ssum[256];
    const int tid = threadIdx.x;
    const int base = blockIdx.x * 1024 + tid * 4;
    int v[4];
#pragma unroll
    for (int j = 0; j < 4; j++) {
        int idx = base + j;
        v[j] = (idx < NN) ? g_cnt[idx] : 0;
        if (idx < NN) g_dinv[idx] = rsqrtf((float)v[j] + 1.0f);
    }
    int s = v[0] + v[1] + v[2] + v[3];
    ssum[tid] = s;
    __syncthreads();
    for (int d = 1; d < 256; d <<= 1) {
        int t = (tid >= d) ? ssum[tid - d] : 0;
        __syncthreads();
        ssum[tid] += t;
        __syncthreads();
    }
    int run = ssum[tid] - s;
#pragma unroll
    for (int j = 0; j < 4; j++) {
        int idx = base + j;
        if (idx < NN) g_off[idx] = run;
        run += v[j];
    }
    if (tid == 255) g_bsum[blockIdx.x] = ssum[255];
}

__global__ void scan2_kernel() {
    __shared__ int s[128];
    const int tid = threadIdx.x;
    int v = (tid < NBLK) ? g_bsum[tid] : 0;
    s[tid] = v;
    __syncthreads();
    for (int d = 1; d < 128; d <<= 1) {
        int t = (tid >= d) ? s[tid - d] : 0;
        __syncthreads();
        s[tid] += t;
        __syncthreads();
    }
    g_bsum[tid] = s[tid] - v;
}

__global__ void scan3_kernel() {
    int i = blockIdx.x * blockDim.x + threadIdx.x;
    if (i < NN) {
        int off = g_off[i] + g_bsum[i >> 10];
        g_off[i] = off;
        g_cur[i] = off;
    }
    if (i == 0) g_off[NN] = EE;
}

__global__ void scatter_kernel(const int* __restrict__ ei) {
    int e = blockIdx.x * blockDim.x + threadIdx.x;
    if (e >= EE) return;
    int src = ei[e];
    int dst = ei[EE + e];
    int pos = atomicAdd(&g_cur[dst], 1);
    g_csr[pos] = src;
}

// ---------------------------------------------------------------------------
// Aggregation u = A_hat * z, CSR, atomic-free.
template <int DIM>
__global__ void agg_kernel(const float* __restrict__ z, float* __restrict__ u) {
    constexpr int GPN = DIM / 4;
    constexpr int SH = (DIM == 64) ? 4 : 5;
    const int gt = blockIdx.x * 256 + threadIdx.x;
    const int node = gt >> SH;
    if (node >= NN) return;
    const int q = gt & (GPN - 1);
    const float dd = g_dinv[node];
    const int s = g_off[node], e = g_off[node + 1];
    const float4* Z = (const float4*)z;
    float4 v0 = Z[(size_t)node * GPN + q];
    float ax = dd * v0.x, ay = dd * v0.y, az = dd * v0.z, aw = dd * v0.w;
    int i = s;
    for (; i + 1 < e; i += 2) {
        int s0 = g_csr[i], s1 = g_csr[i + 1];
        float d0 = g_dinv[s0], d1 = g_dinv[s1];
        float4 a = Z[(size_t)s0 * GPN + q];
        float4 b = Z[(size_t)s1 * GPN + q];
        ax += d0 * a.x + d1 * b.x;
        ay += d0 * a.y + d1 * b.y;
        az += d0 * a.z + d1 * b.z;
        aw += d0 * a.w + d1 * b.w;
    }
    if (i < e) {
        int s0 = g_csr[i];
        float d0 = g_dinv[s0];
        float4 a = Z[(size_t)s0 * GPN + q];
        ax += d0 * a.x; ay += d0 * a.y; az += d0 * a.z; aw += d0 * a.w;
    }
    ((float4*)u)[(size_t)node * GPN + q] = make_float4(dd * ax, dd * ay, dd * az, dd * aw);
}

// ---------------------------------------------------------------------------
// Tensor-core GEMM (3xTF32): Z[N,128] = act(A[N,K] @ W[K,128] + b).
// 256 threads, block tile 64x128, warp tile 32x32, K-chunk 32.
// hi/lo tf32 split stored interleaved (float2) in smem; XOR-swizzled banks.

__device__ __forceinline__ uint32_t f2tf32(float f) {
    uint32_t r;
    asm("cvt.rna.tf32.f32 %0, %1;" : "=r"(r) : "f"(f));
    return r;
}

__device__ __forceinline__ void mma_tf32(float* d, const uint32_t* a, const uint32_t* b) {
    asm volatile(
        "mma.sync.aligned.m16n8k8.row.col.f32.tf32.tf32.f32 "
        "{%0,%1,%2,%3}, {%4,%5,%6,%7}, {%8,%9}, {%0,%1,%2,%3};"
        : "+f"(d[0]), "+f"(d[1]), "+f"(d[2]), "+f"(d[3])
        : "r"(a[0]), "r"(a[1]), "r"(a[2]), "r"(a[3]), "r"(b[0]), "r"(b[1]));
}

template <int K, bool RELU, bool POOL>
__global__ void __launch_bounds__(256) gemm_tc_kernel(const float* __restrict__ A,
                                                      const float* __restrict__ W,
                                                      const float* __restrict__ bias,
                                                      float* __restrict__ Z,
                                                      const int* __restrict__ batch) {
    __shared__ float2 Ash[32 * 64];    // [k][row ^ 8*(k&3)] -> (hi, lo)   16 KB
    __shared__ float2 Bsh[32 * 128];   // [k][col ^ 8*(k&3)] -> (hi, lo)   32 KB
    const int tid = threadIdx.x;
    const int lane = tid & 31;
    const int warp = tid >> 5;
    const int wm = warp >> 2;         // 0..1 -> rows wm*32
    const int wn = warp & 3;          // 0..3 -> cols wn*32
    const int blockRow = blockIdx.x * 64;

    float d[2][4][4];
#pragma unroll
    for (int mi = 0; mi < 2; mi++)
#pragma unroll
        for (int ni = 0; ni < 4; ni++)
#pragma unroll
            for (int j = 0; j < 4; j++) d[mi][ni][j] = 0.0f;

    for (int kc = 0; kc < K; kc += 32) {
        // Fill A chunk: 64 rows x 32 k; 512 float4 reads, convert to hi/lo.
#pragma unroll
        for (int it = 0; it < 2; it++) {
            int fi = tid + it * 256;            // 0..511
            int row = fi >> 3;
            int q = fi & 7;                     // k = q*4 .. q*4+3
            int grow = blockRow + row;
            float4 v = (grow < NN)
                ? *(const float4*)(A + (size_t)grow * K + kc + q * 4)
                : make_float4(0.f, 0.f, 0.f, 0.f);
            const float vv[4] = {v.x, v.y, v.z, v.w};
#pragma unroll
            for (int j = 0; j < 4; j++) {
                int k = q * 4 + j;
                uint32_t hi = f2tf32(vv[j]);
                float lo = vv[j] - __uint_as_float(hi);
                uint32_t lo32 = f2tf32(lo);
                Ash[k * 64 + (row ^ (8 * (k & 3)))] =
                    make_float2(__uint_as_float(hi), __uint_as_float(lo32));
            }
        }
        // Fill B chunk: 32 k x 128 cols; 1024 float4 reads.
#pragma unroll
        for (int it = 0; it < 4; it++) {
            int fi = tid + it * 256;            // 0..1023
            int k = fi >> 5;
            int q = fi & 31;                    // col = q*4 .. q*4+3
            float4 v = *(const float4*)(W + (size_t)(kc + k) * HH + q * 4);
            const float vv[4] = {v.x, v.y, v.z, v.w};
#pragma unroll
            for (int j = 0; j < 4; j++) {
                int col = q * 4 + j;
                uint32_t hi = f2tf32(vv[j]);
                float lo = vv[j] - __uint_as_float(hi);
                uint32_t lo32 = f2tf32(lo);
                Bsh[k * 128 + (col ^ (8 * (k & 3)))] =
                    make_float2(__uint_as_float(hi), __uint_as_float(lo32));
            }
        }
        __syncthreads();

#pragma unroll
        for (int ks = 0; ks < 4; ks++) {
            const int kk = ks * 8 + (lane & 3);
            const int s = 8 * (lane & 3);       // swizzle (same for kk and kk+4)
            uint32_t ahi[2][4], alo[2][4], bhi[4][2], blo[4][2];
#pragma unroll
            for (int mi = 0; mi < 2; mi++) {
                int r0 = wm * 32 + mi * 16 + (lane >> 2);
                float2 a0 = Ash[kk * 64 + (r0 ^ s)];
                float2 a1 = Ash[kk * 64 + ((r0 + 8) ^ s)];
                float2 a2 = Ash[(kk + 4) * 64 + (r0 ^ s)];
                float2 a3 = Ash[(kk + 4) * 64 + ((r0 + 8) ^ s)];
                ahi[mi][0] = __float_as_uint(a0.x); alo[mi][0] = __float_as_uint(a0.y);
                ahi[mi][1] = __float_as_uint(a1.x); alo[mi][1] = __float_as_uint(a1.y);
                ahi[mi][2] = __float_as_uint(a2.x); alo[mi][2] = __float_as_uint(a2.y);
                ahi[mi][3] = __float_as_uint(a3.x); alo[mi][3] = __float_as_uint(a3.y);
            }
#pragma unroll
            for (int ni = 0; ni < 4; ni++) {
                int c0 = wn * 32 + ni * 8 + (lane >> 2);
                float2 b0 = Bsh[kk * 128 + (c0 ^ s)];
                float2 b1 = Bsh[(kk + 4) * 128 + (c0 ^ s)];
                bhi[ni][0] = __float_as_uint(b0.x); blo[ni][0] = __float_as_uint(b0.y);
                bhi[ni][1] = __float_as_uint(b1.x); blo[ni][1] = __float_as_uint(b1.y);
            }
#pragma unroll
            for (int mi = 0; mi < 2; mi++)
#pragma unroll
                for (int ni = 0; ni < 4; ni++) {
                    mma_tf32(d[mi][ni], ahi[mi], bhi[ni]);
                    mma_tf32(d[mi][ni], ahi[mi], blo[ni]);
                    mma_tf32(d[mi][ni], alo[mi], bhi[ni]);
                }
        }
        __syncthreads();
    }

    // Epilogue. D frag: c0 -> (row, col), c1 -> (row, col+1), c2/c3 -> row+8.
#pragma unroll
    for (int mi = 0; mi < 2; mi++) {
        int r0 = blockRow + wm * 32 + mi * 16 + (lane >> 2);
#pragma unroll
        for (int ni = 0; ni < 4; ni++) {
            int col = wn * 32 + ni * 8 + (lane & 3) * 2;
            float2 lo2 = make_float2(d[mi][ni][0], d[mi][ni][1]);
            float2 hi2 = make_float2(d[mi][ni][2], d[mi][ni][3]);
            if (!POOL) {
                float2 bb = *(const float2*)(bias + col);
                lo2.x += bb.x; lo2.y += bb.y;
                hi2.x += bb.x; hi2.y += bb.y;
                if (RELU) {
                    lo2.x = fmaxf(lo2.x, 0.f); lo2.y = fmaxf(lo2.y, 0.f);
                    hi2.x = fmaxf(hi2.x, 0.f); hi2.y = fmaxf(hi2.y, 0.f);
                }
                if (r0 < NN) *(float2*)(Z + (size_t)r0 * HH + col) = lo2;
                if (r0 + 8 < NN) *(float2*)(Z + (size_t)(r0 + 8) * HH + col) = hi2;
            } else {
                if (r0 < NN) {
                    float* p = g_pool + batch[r0] * HH + col;
                    asm volatile("red.global.add.v2.f32 [%0], {%1, %2};" ::"l"(p),
                                 "f"(lo2.x), "f"(lo2.y) : "memory");
                }
                if (r0 + 8 < NN) {
                    float* p = g_pool + batch[r0 + 8] * HH + col;
                    asm volatile("red.global.add.v2.f32 [%0], {%1, %2};" ::"l"(p),
                                 "f"(hi2.x), "f"(hi2.y) : "memory");
                }
            }
        }
    }
}

// ---------------------------------------------------------------------------
__global__ void count_kernel(const int* __restrict__ batch) {
    int i = blockIdx.x * blockDim.x + threadIdx.x;
    if (i < NN) atomicAdd(&g_pool[GG * HH + batch[i]], 1.0f);
}

__global__ void mlp_kernel(const float* __restrict__ b3,
                           const float* __restrict__ fw1, const float* __restrict__ fb1,
                           const float* __restrict__ fw2, const float* __restrict__ fb2,
                           float* __restrict__ out) {
    const int g = blockIdx.x;
    const int j = threadIdx.x;  // 128
    __shared__ float p[HH];
    __shared__ float z[HH];
    const float c = fmaxf(g_pool[GG * HH + g], 1.0f);
    p[j] = g_pool[g * HH + j] / c + b3[j];
    __syncthreads();
    float acc = fb1[j];
#pragma unroll 8
    for (int k = 0; k < HH; k++) acc += p[k] * fw1[k * HH + j];
    z[j] = fmaxf(acc, 0.0f);
    __syncthreads();
    if (j < 4) {
        float o = fb2[j];
#pragma unroll 8
        for (int k = 0; k < HH; k++) o += z[k] * fw2[k * 4 + j];
        out[g * 4 + j] = o;
    }
}

// ---------------------------------------------------------------------------
extern "C" void kernel_launch(void* const* d_in, const int* in_sizes, int n_in,
                              void* d_out, int out_size) {
    const float* x   = (const float*)d_in[0];
    const float* W1  = (const float*)d_in[1];
    const float* b1  = (const float*)d_in[2];
    const float* W2  = (const float*)d_in[3];
    const float* b2  = (const float*)d_in[4];
    const float* W3  = (const float*)d_in[5];
    const float* b3  = (const float*)d_in[6];
    const float* fw1 = (const float*)d_in[7];
    const float* fb1 = (const float*)d_in[8];
    const float* fw2 = (const float*)d_in[9];
    const float* fb2 = (const float*)d_in[10];
    const int*   ei  = (const int*)d_in[11];
    const int*   bat = (const int*)d_in[12];
    float* out = (float*)d_out;

    float *du, *dz, *dpool;
    int *dcnt;
    cudaGetSymbolAddress((void**)&du, g_u);
    cudaGetSymbolAddress((void**)&dz, g_z);
    cudaGetSymbolAddress((void**)&dpool, g_pool);
    cudaGetSymbolAddress((void**)&dcnt, g_cnt);

    // --- CSR build (also yields degrees -> dinv) ---
    zero_int_kernel<<<(NN + 255) / 256, 256>>>(dcnt, NN);
    zero_f_kernel<<<(GG * HH + GG + 255) / 256, 256>>>(dpool, GG * HH + GG);
    hist_kernel<<<(EE + 255) / 256, 256>>>(ei);
    scan1_kernel<<<NBLK, 256>>>();
    scan2_kernel<<<1, 128>>>();
    scan3_kernel<<<(NN + 255) / 256, 256>>>();
    scatter_kernel<<<(EE + 255) / 256, 256>>>(ei);

    const int GEMM_GRID = (NN + 63) / 64;  // 1563

    // Layer 1: u = A_hat x (64-dim), z = relu(u W1 + b1)
    agg_kernel<FIN><<<(NN * 16 + 255) / 256, 256>>>(x, du);
    gemm_tc_kernel<FIN, true, false><<<GEMM_GRID, 256>>>(du, W1, b1, dz, nullptr);

    // Layer 2
    agg_kernel<HH><<<(NN * 32 + 255) / 256, 256>>>(dz, du);
    gemm_tc_kernel<HH, true, false><<<GEMM_GRID, 256>>>(du, W2, b2, dz, nullptr);

    // Layer 3: GEMM reduces directly into pool (bias b3 folded into MLP)
    agg_kernel<HH><<<(NN * 32 + 255) / 256, 256>>>(dz, du);
    gemm_tc_kernel<HH, false, true><<<GEMM_GRID, 256>>>(du, W3, nullptr, nullptr, bat);

    count_kernel<<<(NN + 255) / 256, 256>>>(bat);
    mlp_kernel<<<GG, HH>>>(b3, fw1, fb1, fw2, fb2, out);
}